// round 9
// baseline (speedup 1.0000x reference)
#include <cuda_runtime.h>
#include <cstdint>

#define B        2
#define N_PRE    50000
#define N_POST   50000
#define N_SYN    10000000
#define N_TYPES  20
#define N_BASIS  5

#define MASK_WORDS (N_PRE / 16)          // 3125 words (2 bits/neuron)
#define N_ROWS     (B * N_POST)          // 100000
#define THREADS    256

__device__ uint32_t g_spike_mask[MASK_WORDS];
// Per-(batch,post) x type weight sums. Zero at module load; phase C re-zeroes
// after reading, so it is zero at entry of EVERY kernel_launch call.
__device__ __align__(16) float g_S[N_ROWS * N_TYPES];   // 8 MB, L2-resident

// Self-resetting grid barriers (two instances, each used once per launch).
__device__ unsigned g_cnt0 = 0, g_cnt1 = 0;
__device__ volatile unsigned g_flag0 = 0, g_flag1 = 0;

__device__ __forceinline__ void grid_barrier(unsigned* cnt, volatile unsigned* flag,
                                             unsigned total)
{
    __threadfence();          // make this thread's prior writes visible device-wide
    __syncthreads();
    if (threadIdx.x == 0) {
        unsigned before = *flag;
        unsigned old = atomicAdd(cnt, 1u);
        if (old == total - 1) {
            *cnt = 0;
            __threadfence();
            *flag = before + 1;            // release
        } else {
            while (*flag == before) { __nanosleep(64); }
        }
        __threadfence();
    }
    __syncthreads();
}

// One firing synapse: 2 lazy gathers + <=2 scalar reductions into S.
__device__ __forceinline__ void emit_syn(uint32_t m, int syn, int post,
                                         const float* __restrict__ weights,
                                         const int*   __restrict__ syn_ids)
{
    if (m == 0u) return;
    float w = __ldg(weights + syn);
    int   t = __ldg(syn_ids + syn);
    if (m & 1u) atomicAdd(g_S + (size_t)post * N_TYPES + t, w);
    if (m & 2u) atomicAdd(g_S + ((size_t)N_POST + post) * N_TYPES + t, w);
}

__global__ __launch_bounds__(THREADS)
void fused_kernel(const float* __restrict__ spikes,
                  const float* __restrict__ weights,
                  const float* __restrict__ basis,
                  const int4*  __restrict__ syn_idx4,
                  const int*   __restrict__ syn_ids,
                  float*       __restrict__ out)
{
    __shared__ uint32_t smask[MASK_WORDS];
    __shared__ float sb[N_TYPES * N_BASIS];
    __shared__ float srow[THREADS * N_BASIS];

    const unsigned nblocks = gridDim.x;
    const int gtid = blockIdx.x * THREADS + threadIdx.x;
    const int gstride = nblocks * THREADS;

    // ---- Phase A: build packed 2-bit spike mask (ballot) -------------------
    for (int n0 = gtid * 32; n0 < N_PRE + 31; n0 += gstride * 32) {
        // each thread handles neuron n = n0-block mapping via its lane:
        // simpler: thread handles neuron idx = (warp-global)*32 + lane
        break;  // (structured below)
    }
    {
        // one thread per neuron, grid-stride by full warps
        int warp_global = gtid >> 5;
        int lane = threadIdx.x & 31;
        int nwarps = gstride >> 5;
        int total_warp_iters = (N_PRE + 31) / 32;       // 1563
        for (int wi = warp_global; wi < total_warp_iters; wi += nwarps) {
            int n = wi * 32 + lane;
            bool f0 = false, f1 = false;
            if (n < N_PRE) {
                f0 = (__ldg(spikes + n) != 0.0f);
                f1 = (__ldg(spikes + N_PRE + n) != 0.0f);
            }
            uint32_t b0 = __ballot_sync(0xFFFFFFFFu, f0);
            uint32_t b1 = __ballot_sync(0xFFFFFFFFu, f1);
            if (lane == 0 || lane == 16) {
                uint32_t h0 = (b0 >> lane) & 0xFFFFu;
                uint32_t h1 = (b1 >> lane) & 0xFFFFu;
                uint32_t m = 0;
                #pragma unroll
                for (int j = 0; j < 16; j++)
                    m |= (((h0 >> j) & 1u) | (((h1 >> j) & 1u) << 1)) << (2 * j);
                int w = (n >> 4);
                if (w < MASK_WORDS) g_spike_mask[w] = m;
            }
        }
    }

    grid_barrier(&g_cnt0, &g_flag0, nblocks);

    // ---- Phase B: scatter-accumulate into g_S ------------------------------
    for (int i = threadIdx.x; i < MASK_WORDS; i += THREADS)
        smask[i] = g_spike_mask[i];
    __syncthreads();

    const int NG = N_SYN / 4;
    for (int g = gtid; g < NG; g += gstride) {
        int4 u = __ldcs(syn_idx4 + g * 2);
        int4 v = __ldcs(syn_idx4 + g * 2 + 1);

        uint32_t m0 = (smask[u.y >> 4] >> ((u.y & 15) << 1)) & 3u;
        uint32_t m1 = (smask[u.w >> 4] >> ((u.w & 15) << 1)) & 3u;
        uint32_t m2 = (smask[v.y >> 4] >> ((v.y & 15) << 1)) & 3u;
        uint32_t m3 = (smask[v.w >> 4] >> ((v.w & 15) << 1)) & 3u;

        if ((m0 | m1 | m2 | m3) == 0u) continue;   // ~85% of groups

        int s = g * 4;
        emit_syn(m0, s + 0, u.x, weights, syn_ids);
        emit_syn(m1, s + 1, u.z, weights, syn_ids);
        emit_syn(m2, s + 2, v.x, weights, syn_ids);
        emit_syn(m3, s + 3, v.z, weights, syn_ids);
    }

    grid_barrier(&g_cnt1, &g_flag1, nblocks);

    // ---- Phase C: compact  out = S @ basis, re-zero S ----------------------
    if (threadIdx.x < N_TYPES * N_BASIS) sb[threadIdx.x] = basis[threadIdx.x];
    __syncthreads();

    const int n_tiles = (N_ROWS + THREADS - 1) / THREADS;   // 391
    for (int tb = blockIdx.x; tb < n_tiles; tb += nblocks) {
        int row = tb * THREADS + threadIdx.x;
        if (row < N_ROWS) {
            float4* S4 = (float4*)(g_S + (size_t)row * N_TYPES);
            float4 a = S4[0], b = S4[1], c = S4[2], d = S4[3], e = S4[4];
            float s[N_TYPES] = {a.x,a.y,a.z,a.w, b.x,b.y,b.z,b.w,
                                c.x,c.y,c.z,c.w, d.x,d.y,d.z,d.w,
                                e.x,e.y,e.z,e.w};
            #pragma unroll
            for (int r = 0; r < N_BASIS; r++) {
                float acc = 0.f;
                #pragma unroll
                for (int t = 0; t < N_TYPES; t++)
                    acc += s[t] * sb[t * N_BASIS + r];
                srow[threadIdx.x * N_BASIS + r] = acc;
            }
            float4 z = make_float4(0.f, 0.f, 0.f, 0.f);
            S4[0] = z; S4[1] = z; S4[2] = z; S4[3] = z; S4[4] = z;
        }
        __syncthreads();

        const int total4 = (N_ROWS * N_BASIS) / 4;        // 125000 float4
        int base4 = tb * (THREADS * N_BASIS / 4);         // tb * 320
        float4* out4 = (float4*)out;
        for (int i = threadIdx.x; i < THREADS * N_BASIS / 4; i += THREADS) {
            int o4 = base4 + i;
            if (o4 < total4) {
                const float* p = srow + i * 4;
                out4[o4] = make_float4(p[0], p[1], p[2], p[3]);
            }
        }
        __syncthreads();
    }
}

extern "C" void kernel_launch(void* const* d_in, const int* in_sizes, int n_in,
                              void* d_out, int out_size)
{
    const float* spikes  = (const float*)d_in[0];
    const float* weights = (const float*)d_in[1];
    const float* basis   = (const float*)d_in[2];
    const int4*  syn_idx = (const int4*)d_in[3];
    const int*   syn_ids = (const int*)d_in[4];
    float* out = (float*)d_out;

    // Grid sized to guaranteed co-residency so the spin barriers are safe.
    int nsm = 0, nb_per_sm = 0;
    cudaDeviceGetAttribute(&nsm, cudaDevAttrMultiProcessorCount, 0);
    cudaOccupancyMaxActiveBlocksPerMultiprocessor(&nb_per_sm, fused_kernel,
                                                  THREADS, 0);
    if (nb_per_sm < 1) nb_per_sm = 1;
    int grid = nsm * nb_per_sm;

    fused_kernel<<<grid, THREADS>>>(spikes, weights, basis, syn_idx, syn_ids, out);
}

// round 10
// speedup vs baseline: 1.4187x; 1.4187x over previous
#include <cuda_runtime.h>
#include <cstdint>

#define B        2
#define N_PRE    50000
#define N_POST   50000
#define N_SYN    10000000
#define N_TYPES  20
#define N_BASIS  5

#define MASK_WORDS (N_PRE / 16)          // 3125 words (2 bits/neuron)
#define N_ROWS     (B * N_POST)          // 100000

__device__ uint32_t g_spike_mask[MASK_WORDS];
// Per-(batch,post) x type weight sums. Zero at module load; compact_kernel
// re-zeroes after reading, so it is zero at entry of EVERY kernel_launch call.
__device__ __align__(16) float g_S[N_ROWS * N_TYPES];   // 8 MB, L2-resident

// ---------------------------------------------------------------------------
// prep: ballot-based packed 2-bit spike mask.
__global__ void prep_kernel(const float* __restrict__ spikes)
{
    int tid = blockIdx.x * blockDim.x + threadIdx.x;
    if (tid >= ((N_PRE + 31) & ~31)) return;
    int n = tid;
    bool f0 = false, f1 = false;
    if (n < N_PRE) {
        f0 = (__ldg(spikes + n) != 0.0f);
        f1 = (__ldg(spikes + N_PRE + n) != 0.0f);
    }
    uint32_t b0 = __ballot_sync(0xFFFFFFFFu, f0);
    uint32_t b1 = __ballot_sync(0xFFFFFFFFu, f1);
    int lane = threadIdx.x & 31;
    if (lane == 0 || lane == 16) {
        uint32_t h0 = (b0 >> lane) & 0xFFFFu;
        uint32_t h1 = (b1 >> lane) & 0xFFFFu;
        uint32_t m = 0;
        #pragma unroll
        for (int j = 0; j < 16; j++)
            m |= (((h0 >> j) & 1u) | (((h1 >> j) & 1u) << 1)) << (2 * j);
        int w = (n >> 4);
        if (w < MASK_WORDS) g_spike_mask[w] = m;
    }
}

// ---------------------------------------------------------------------------
__global__ __launch_bounds__(256)
void accum_kernel(const float* __restrict__ weights,       // [N_SYN]
                  const int4*  __restrict__ syn_idx4,      // [N_SYN/2]
                  const int4*  __restrict__ syn_ids4)      // [N_SYN/4]
{
    __shared__ uint32_t smask[MASK_WORDS];
    for (int i = threadIdx.x; i < MASK_WORDS; i += blockDim.x)
        smask[i] = g_spike_mask[i];
    __syncthreads();

    const int NG = N_SYN / 4;                 // 4 consecutive synapses / thread
    const int stride = gridDim.x * blockDim.x;

    for (int g = blockIdx.x * blockDim.x + threadIdx.x; g < NG; g += stride) {
        int4 u = __ldcs(syn_idx4 + g * 2);     // syn 4g+0:(u.x,u.y) 4g+1:(u.z,u.w)
        int4 v = __ldcs(syn_idx4 + g * 2 + 1); // syn 4g+2:(v.x,v.y) 4g+3:(v.z,v.w)

        uint32_t m0 = (smask[u.y >> 4] >> ((u.y & 15) << 1)) & 3u;
        uint32_t m1 = (smask[u.w >> 4] >> ((u.w & 15) << 1)) & 3u;
        uint32_t m2 = (smask[v.y >> 4] >> ((v.y & 15) << 1)) & 3u;
        uint32_t m3 = (smask[v.w >> 4] >> ((v.w & 15) << 1)) & 3u;

        if ((m0 | m1 | m2 | m3) == 0u) continue;   // ~85% of lanes skip

        // Branchless heavy path: two vector gathers (contiguous 16B each),
        // then 8 predicated scalar reductions.
        float4 wv = __ldg((const float4*)(weights + g * 4));
        int4   tt = __ldg(syn_ids4 + g);

        float* r0 = g_S + (size_t)u.x * N_TYPES + tt.x;
        float* r1 = g_S + (size_t)u.z * N_TYPES + tt.y;
        float* r2 = g_S + (size_t)v.x * N_TYPES + tt.z;
        float* r3 = g_S + (size_t)v.z * N_TYPES + tt.w;
        const size_t OFF = (size_t)N_POST * N_TYPES;   // batch-1 row offset

        if (m0 & 1u) atomicAdd(r0,       wv.x);
        if (m0 & 2u) atomicAdd(r0 + OFF, wv.x);
        if (m1 & 1u) atomicAdd(r1,       wv.y);
        if (m1 & 2u) atomicAdd(r1 + OFF, wv.y);
        if (m2 & 1u) atomicAdd(r2,       wv.z);
        if (m2 & 2u) atomicAdd(r2 + OFF, wv.z);
        if (m3 & 1u) atomicAdd(r3,       wv.w);
        if (m3 & 2u) atomicAdd(r3 + OFF, wv.w);
    }
}

// ---------------------------------------------------------------------------
// compact: out[row][r] = sum_t S[row][t] * basis[t][r]; then zero S[row].
__global__ __launch_bounds__(256)
void compact_kernel(const float* __restrict__ basis, float* __restrict__ out)
{
    __shared__ float sb[N_TYPES * N_BASIS];
    __shared__ float srow[256 * N_BASIS];

    int tid = threadIdx.x;
    if (tid < N_TYPES * N_BASIS) sb[tid] = basis[tid];
    __syncthreads();

    int row = blockIdx.x * 256 + tid;
    if (row < N_ROWS) {
        float4* S4 = (float4*)(g_S + (size_t)row * N_TYPES);   // 20 floats
        float4 a = S4[0], b = S4[1], c = S4[2], d = S4[3], e = S4[4];
        float s[N_TYPES] = {a.x,a.y,a.z,a.w, b.x,b.y,b.z,b.w, c.x,c.y,c.z,c.w,
                            d.x,d.y,d.z,d.w, e.x,e.y,e.z,e.w};
        #pragma unroll
        for (int r = 0; r < N_BASIS; r++) {
            float acc = 0.f;
            #pragma unroll
            for (int t = 0; t < N_TYPES; t++)
                acc += s[t] * sb[t * N_BASIS + r];
            srow[tid * N_BASIS + r] = acc;
        }
        // Re-zero S for the next kernel_launch call (invariant).
        float4 z = make_float4(0.f, 0.f, 0.f, 0.f);
        S4[0] = z; S4[1] = z; S4[2] = z; S4[3] = z; S4[4] = z;
    }
    __syncthreads();

    const int total4 = (N_ROWS * N_BASIS) / 4;        // 125000 float4
    int base4 = blockIdx.x * 320;
    float4* out4 = (float4*)out;
    for (int i = tid; i < 320; i += 256) {
        int o4 = base4 + i;
        if (o4 < total4) {
            const float* p = srow + i * 4;
            out4[o4] = make_float4(p[0], p[1], p[2], p[3]);
        }
    }
}

extern "C" void kernel_launch(void* const* d_in, const int* in_sizes, int n_in,
                              void* d_out, int out_size)
{
    const float* spikes  = (const float*)d_in[0];   // rec_z_buf [B, N_PRE]
    const float* weights = (const float*)d_in[1];   // weight_values [N_SYN]
    const float* basis   = (const float*)d_in[2];   // synaptic_basis_weights [20,5]
    const int4*  syn_idx = (const int4*)d_in[3];    // synapse_indices [N_SYN,2]
    const int4*  syn_ids = (const int4*)d_in[4];    // syn_ids [N_SYN]
    float* out = (float*)d_out;                     // [B*N_POST, N_BASIS]

    prep_kernel<<<196, 256>>>(spikes);

    accum_kernel<<<1184, 256>>>(weights, syn_idx, syn_ids);

    compact_kernel<<<(N_ROWS + 255) / 256, 256>>>(basis, out);
}

// round 11
// speedup vs baseline: 1.5650x; 1.1031x over previous
#include <cuda_runtime.h>
#include <cstdint>

#define B        2
#define N_PRE    50000
#define N_POST   50000
#define N_SYN    10000000
#define N_TYPES  20
#define N_BASIS  5

#define MASK_WORDS (N_PRE / 16)          // 3125 words (2 bits/neuron)
#define N_ROWS     (B * N_POST)          // 100000

__device__ uint32_t g_spike_mask[MASK_WORDS];
// Per-(batch,post) x type weight sums. Zero at module load; compact_kernel
// re-zeroes after reading, so it is zero at entry of EVERY kernel_launch call.
__device__ __align__(16) float g_S[N_ROWS * N_TYPES];   // 8 MB, L2-resident

// ---------------------------------------------------------------------------
// prep: ballot-based packed 2-bit spike mask.
__global__ void prep_kernel(const float* __restrict__ spikes)
{
    int tid = blockIdx.x * blockDim.x + threadIdx.x;
    if (tid >= ((N_PRE + 31) & ~31)) return;
    int n = tid;
    bool f0 = false, f1 = false;
    if (n < N_PRE) {
        f0 = (__ldg(spikes + n) != 0.0f);
        f1 = (__ldg(spikes + N_PRE + n) != 0.0f);
    }
    uint32_t b0 = __ballot_sync(0xFFFFFFFFu, f0);
    uint32_t b1 = __ballot_sync(0xFFFFFFFFu, f1);
    int lane = threadIdx.x & 31;
    if (lane == 0 || lane == 16) {
        uint32_t h0 = (b0 >> lane) & 0xFFFFu;
        uint32_t h1 = (b1 >> lane) & 0xFFFFu;
        uint32_t m = 0;
        #pragma unroll
        for (int j = 0; j < 16; j++)
            m |= (((h0 >> j) & 1u) | (((h1 >> j) & 1u) << 1)) << (2 * j);
        int w = (n >> 4);
        if (w < MASK_WORDS) g_spike_mask[w] = m;
    }
}

// ---------------------------------------------------------------------------
__global__ __launch_bounds__(256)
void accum_kernel(const float* __restrict__ weights,       // [N_SYN]
                  const int4*  __restrict__ syn_idx4,      // [N_SYN/2]
                  const int4*  __restrict__ syn_ids4)      // [N_SYN/4]
{
    __shared__ uint32_t smask[MASK_WORDS];

    // Wait for prep (PDL): everything above/before this point overlapped
    // with prep's execution (block launch, smem alloc, const setup).
    cudaGridDependencySynchronize();

    for (int i = threadIdx.x; i < MASK_WORDS; i += blockDim.x)
        smask[i] = g_spike_mask[i];
    __syncthreads();

    const int NG = N_SYN / 4;                 // 4 consecutive synapses / thread
    const int stride = gridDim.x * blockDim.x;

    for (int g = blockIdx.x * blockDim.x + threadIdx.x; g < NG; g += stride) {
        int4 u = __ldcs(syn_idx4 + g * 2);     // syn 4g+0:(u.x,u.y) 4g+1:(u.z,u.w)
        int4 v = __ldcs(syn_idx4 + g * 2 + 1); // syn 4g+2:(v.x,v.y) 4g+3:(v.z,v.w)

        uint32_t m0 = (smask[u.y >> 4] >> ((u.y & 15) << 1)) & 3u;
        uint32_t m1 = (smask[u.w >> 4] >> ((u.w & 15) << 1)) & 3u;
        uint32_t m2 = (smask[v.y >> 4] >> ((v.y & 15) << 1)) & 3u;
        uint32_t m3 = (smask[v.w >> 4] >> ((v.w & 15) << 1)) & 3u;

        if ((m0 | m1 | m2 | m3) == 0u) continue;   // ~85% of lanes skip

        float4 wv = __ldg((const float4*)(weights + g * 4));
        int4   tt = __ldg(syn_ids4 + g);

        float* r0 = g_S + (size_t)u.x * N_TYPES + tt.x;
        float* r1 = g_S + (size_t)u.z * N_TYPES + tt.y;
        float* r2 = g_S + (size_t)v.x * N_TYPES + tt.z;
        float* r3 = g_S + (size_t)v.z * N_TYPES + tt.w;
        const size_t OFF = (size_t)N_POST * N_TYPES;   // batch-1 row offset

        if (m0 & 1u) atomicAdd(r0,       wv.x);
        if (m0 & 2u) atomicAdd(r0 + OFF, wv.x);
        if (m1 & 1u) atomicAdd(r1,       wv.y);
        if (m1 & 2u) atomicAdd(r1 + OFF, wv.y);
        if (m2 & 1u) atomicAdd(r2,       wv.z);
        if (m2 & 2u) atomicAdd(r2 + OFF, wv.z);
        if (m3 & 1u) atomicAdd(r3,       wv.w);
        if (m3 & 2u) atomicAdd(r3 + OFF, wv.w);
    }
}

// ---------------------------------------------------------------------------
// compact: out[row][r] = sum_t S[row][t] * basis[t][r]; then zero S[row].
__global__ __launch_bounds__(256)
void compact_kernel(const float* __restrict__ basis, float* __restrict__ out)
{
    __shared__ float sb[N_TYPES * N_BASIS];
    __shared__ float srow[256 * N_BASIS];

    int tid = threadIdx.x;
    // Preamble independent of accum's output: stage basis in smem.
    if (tid < N_TYPES * N_BASIS) sb[tid] = basis[tid];
    __syncthreads();

    // Wait for accum (PDL) before touching g_S.
    cudaGridDependencySynchronize();

    int row = blockIdx.x * 256 + tid;
    if (row < N_ROWS) {
        float4* S4 = (float4*)(g_S + (size_t)row * N_TYPES);   // 20 floats
        float4 a = S4[0], b = S4[1], c = S4[2], d = S4[3], e = S4[4];
        float s[N_TYPES] = {a.x,a.y,a.z,a.w, b.x,b.y,b.z,b.w, c.x,c.y,c.z,c.w,
                            d.x,d.y,d.z,d.w, e.x,e.y,e.z,e.w};
        #pragma unroll
        for (int r = 0; r < N_BASIS; r++) {
            float acc = 0.f;
            #pragma unroll
            for (int t = 0; t < N_TYPES; t++)
                acc += s[t] * sb[t * N_BASIS + r];
            srow[tid * N_BASIS + r] = acc;
        }
        // Re-zero S for the next kernel_launch call (invariant).
        float4 z = make_float4(0.f, 0.f, 0.f, 0.f);
        S4[0] = z; S4[1] = z; S4[2] = z; S4[3] = z; S4[4] = z;
    }
    __syncthreads();

    const int total4 = (N_ROWS * N_BASIS) / 4;        // 125000 float4
    int base4 = blockIdx.x * 320;
    float4* out4 = (float4*)out;
    for (int i = tid; i < 320; i += 256) {
        int o4 = base4 + i;
        if (o4 < total4) {
            const float* p = srow + i * 4;
            out4[o4] = make_float4(p[0], p[1], p[2], p[3]);
        }
    }
}

extern "C" void kernel_launch(void* const* d_in, const int* in_sizes, int n_in,
                              void* d_out, int out_size)
{
    const float* spikes  = (const float*)d_in[0];   // rec_z_buf [B, N_PRE]
    const float* weights = (const float*)d_in[1];   // weight_values [N_SYN]
    const float* basis   = (const float*)d_in[2];   // synaptic_basis_weights [20,5]
    const int4*  syn_idx = (const int4*)d_in[3];    // synapse_indices [N_SYN,2]
    const int4*  syn_ids = (const int4*)d_in[4];    // syn_ids [N_SYN]
    float* out = (float*)d_out;                     // [B*N_POST, N_BASIS]

    // prep: normal launch.
    prep_kernel<<<196, 256>>>(spikes);

    // accum: PDL secondary — may begin during prep; syncs internally.
    {
        cudaLaunchAttribute attr[1];
        attr[0].id = cudaLaunchAttributeProgrammaticStreamSerialization;
        attr[0].val.programmaticStreamSerializationAllowed = 1;
        cudaLaunchConfig_t cfg = {};
        cfg.gridDim  = dim3(1184, 1, 1);
        cfg.blockDim = dim3(256, 1, 1);
        cfg.dynamicSmemBytes = 0;
        cfg.stream = 0;
        cfg.attrs = attr;
        cfg.numAttrs = 1;
        cudaLaunchKernelEx(&cfg, accum_kernel, weights, syn_idx, syn_ids);
    }

    // compact: PDL secondary — ramp + basis staging overlap accum's tail.
    {
        cudaLaunchAttribute attr[1];
        attr[0].id = cudaLaunchAttributeProgrammaticStreamSerialization;
        attr[0].val.programmaticStreamSerializationAllowed = 1;
        cudaLaunchConfig_t cfg = {};
        cfg.gridDim  = dim3((N_ROWS + 255) / 256, 1, 1);
        cfg.blockDim = dim3(256, 1, 1);
        cfg.dynamicSmemBytes = 0;
        cfg.stream = 0;
        cfg.attrs = attr;
        cfg.numAttrs = 1;
        cudaLaunchKernelEx(&cfg, compact_kernel, basis, out);
    }
}